// round 15
// baseline (speedup 1.0000x reference)
#include <cuda_runtime.h>
#include <cuda_fp16.h>
#include <cstdint>
#include <math.h>

// ---------------- problem constants ----------------
#define BATCH    16384
#define F_IN     768
#define F_OUT    512
#define BM       64            // batch rows per unit
#define BN       256           // output cols per unit (n-half)
#define BK       64            // K chunk
#define NCHUNK   (F_IN / BK)   // 12 chunks per unit
#define NTHREADS 256
#define NCTA     148           // persistent CTAs (safe for 148- or 152-SM parts)
#define NUNITS   1024          // 256 m-tiles x 2 passes x 2 n-halves

// ---------------- smem layout (bytes) ----------------
#define SM_RED   0                     // 64 f32
#define SM_A0    4096                  // 2 stages x 8192 (64 rows x 128B)
#define SM_B     20480                 // 2 stages x 32768 (256 rows x 128B)
#define SM_TOTAL (SM_B + 2 * 32768)    // 86016

// ---------------- helpers ----------------
__device__ __forceinline__ uint32_t smem_u32(const void* p) {
    uint32_t a;
    asm("{ .reg .u64 t; cvta.to.shared.u64 t, %1; cvt.u32.u64 %0, t; }" : "=r"(a) : "l"(p));
    return a;
}

#define LDSM_X4(r0, r1, r2, r3, addr) \
    asm volatile("ldmatrix.sync.aligned.m8n8.x4.shared.b16 {%0,%1,%2,%3}, [%4];" \
                 : "=r"(r0), "=r"(r1), "=r"(r2), "=r"(r3) : "r"(addr))

#define MMA16816(d, a, b) \
    asm volatile("mma.sync.aligned.m16n8k16.row.col.f32.f16.f16.f32 " \
                 "{%0,%1,%2,%3}, {%4,%5,%6,%7}, {%8,%9}, {%0,%1,%2,%3};" \
                 : "+f"((d)[0]), "+f"((d)[1]), "+f"((d)[2]), "+f"((d)[3]) \
                 : "r"((a)[0]), "r"((a)[1]), "r"((a)[2]), "r"((a)[3]), \
                   "r"((b)[0]), "r"((b)[1]))

#define CP_ASYNC16(dst, src) \
    asm volatile("cp.async.cg.shared.global [%0], [%1], 16;" :: "r"(dst), "l"(src) : "memory")
#define CP_COMMIT() asm volatile("cp.async.commit_group;" ::: "memory")
#define CP_WAIT0()  asm volatile("cp.async.wait_group 0;" ::: "memory")

// cvt 8 f32 -> 8 f16, one swizzled 16B STS
__device__ __forceinline__ void sts_a16(uint32_t addr, float4 v0, float4 v1) {
    uint32_t u0, u1, u2, u3;
    asm("cvt.rn.f16x2.f32 %0, %1, %2;" : "=r"(u0) : "f"(v0.y), "f"(v0.x));
    asm("cvt.rn.f16x2.f32 %0, %1, %2;" : "=r"(u1) : "f"(v0.w), "f"(v0.z));
    asm("cvt.rn.f16x2.f32 %0, %1, %2;" : "=r"(u2) : "f"(v1.y), "f"(v1.x));
    asm("cvt.rn.f16x2.f32 %0, %1, %2;" : "=r"(u3) : "f"(v1.w), "f"(v1.z));
    asm volatile("st.shared.v4.u32 [%0], {%1,%2,%3,%4};"
                 :: "r"(addr), "r"(u0), "r"(u1), "r"(u2), "r"(u3) : "memory");
}

// ---------------- device globals ----------------
__device__ __align__(16) __half g_W1h[F_OUT * F_IN];
__device__ float g_part[4][BATCH];   // [pass*2 + nhalf][row], each written once per launch

__global__ void __launch_bounds__(512) convert_w1_kernel(const float* __restrict__ W1) {
    // 48 blocks x 512 threads x 4 independent float4 (MLP=4)
    const int base = blockIdx.x * 2048 + threadIdx.x;
    float4 v0 = reinterpret_cast<const float4*>(W1)[base];
    float4 v1 = reinterpret_cast<const float4*>(W1)[base + 512];
    float4 v2 = reinterpret_cast<const float4*>(W1)[base + 1024];
    float4 v3 = reinterpret_cast<const float4*>(W1)[base + 1536];
    __half2* dst = reinterpret_cast<__half2*>(g_W1h);
    dst[(base)        * 2]     = __floats2half2_rn(v0.x, v0.y);
    dst[(base)        * 2 + 1] = __floats2half2_rn(v0.z, v0.w);
    dst[(base + 512)  * 2]     = __floats2half2_rn(v1.x, v1.y);
    dst[(base + 512)  * 2 + 1] = __floats2half2_rn(v1.z, v1.w);
    dst[(base + 1024) * 2]     = __floats2half2_rn(v2.x, v2.y);
    dst[(base + 1024) * 2 + 1] = __floats2half2_rn(v2.z, v2.w);
    dst[(base + 1536) * 2]     = __floats2half2_rn(v3.x, v3.y);
    dst[(base + 1536) * 2 + 1] = __floats2half2_rn(v3.z, v3.w);
}

__global__ void __launch_bounds__(256) finalize_kernel(const float* __restrict__ b2,
                                                       float* __restrict__ out) {
    const int i = blockIdx.x * 256 + threadIdx.x;
    const float z = g_part[0][i] + g_part[1][i] + g_part[2][i] + g_part[3][i] + b2[0];
    out[i] = 1.0f / (1.0f + expf(-z));
}

// unit decode: uid = m*4 + pass*2 + nh
#define U_M0(uid)   (((uid) >> 2) * BM)
#define U_PASS(uid) (((uid) >> 1) & 1)
#define U_NH(uid)   ((uid) & 1)

// ---------------- persistent fused perspective-network kernel ----------------
// 148 CTAs x 256 threads. Each CTA processes 6-7 units of (m-tile, n-half, pass),
// 12 K-chunks each, with a FLAT double-buffered cp.async pipeline across unit
// boundaries. 8 warps: warpM = wid>>2 (2 x 32 rows), warpN = wid&3 (4 x 64 cols).
__global__ void __launch_bounds__(NTHREADS, 1)
persp_kernel(const float* __restrict__ stm, const float* __restrict__ nstm,
             const float* __restrict__ b1, const float* __restrict__ W2) {
    extern __shared__ __align__(1024) char smem[];
    const uint32_t sb = smem_u32(smem);
    const int tid  = threadIdx.x;
    const int lane = tid & 31;
    const int wid  = tid >> 5;
    const int warpM = wid >> 2;    // 0..1
    const int warpN = wid & 3;     // 0..3
    const int cta  = blockIdx.x;

    const int myUnits = (cta < (NUNITS - (NUNITS / NCTA) * NCTA)) ? (NUNITS / NCTA + 1)
                                                                  : (NUNITS / NCTA);
    const int nT = myUnits * NCHUNK;

    float* red_s = reinterpret_cast<float*>(smem + SM_RED);
    if (tid < BM) red_s[tid] = 0.0f;

    // ---- ldmatrix per-lane geometry ----
    const int aRow   = warpM * 32 + ((lane >> 3) & 1) * 8 + (lane & 7);
    const uint32_t aXor = ((uint32_t)(lane >> 4) * 16) ^ ((uint32_t)(aRow & 7) << 4);
    const uint32_t aOff = aRow * 128;
    const int bRow   = warpN * 64 + ((lane >> 4) & 1) * 8 + (lane & 7);
    const uint32_t bXor = (((uint32_t)(lane >> 3) & 1) * 16) ^ ((uint32_t)(bRow & 7) << 4);
    const uint32_t bOff = bRow * 128;

    // ---- fill geometry ----
    // A: 64 rows x 64 f32; thread -> row tid>>2, 16 floats at (tid&3)*16
    const int aRowG = tid >> 2;
    const int aSeg  = tid & 3;
    const uint32_t aSts0 = aRowG * 128 + (((uint32_t)aSeg * 32)      ^ ((uint32_t)(aRowG & 7) << 4));
    const uint32_t aSts1 = aRowG * 128 + (((uint32_t)aSeg * 32 + 16) ^ ((uint32_t)(aRowG & 7) << 4));
    // B: 256 rows x 64 f16; thread -> rows (tid>>3)+32j (j<8), 16B seg tid&7
    const int bRow0 = tid >> 3;            // 0..31
    const int bSeg  = tid & 7;
    const uint32_t bDstSw = (((uint32_t)bSeg * 16) ^ ((uint32_t)(bRow0 & 7) << 4));

    float acc[2][8][4] = {};
    float rowsum[4] = {0.f, 0.f, 0.f, 0.f};
    float4 sA[4];    // staged A floats (16) for chunk t+1 at loop head

    // ---- prologue: fill stage0 with (unit0, chunk0); stage A for (unit0, chunk1) ----
    {
        const int uid0 = cta;
        const float* X0 = U_PASS(uid0) ? nstm : stm;
        const int m00 = U_M0(uid0), nh0 = U_NH(uid0);
        const __half* bs = g_W1h + (size_t)(nh0 * BN + bRow0) * F_IN + bSeg * 8;
#pragma unroll
        for (int j = 0; j < 8; ++j)
            CP_ASYNC16(sb + SM_B + (uint32_t)(bRow0 + 32 * j) * 128 + bDstSw,
                       bs + (size_t)(32 * j) * F_IN);
        CP_COMMIT();
        const float4* s0 = reinterpret_cast<const float4*>(
            X0 + (size_t)(m00 + aRowG) * F_IN + aSeg * 16);
        float4 t0 = s0[0], t1 = s0[1], t2 = s0[2], t3 = s0[3];
        sts_a16(sb + SM_A0 + aSts0, t0, t1);
        sts_a16(sb + SM_A0 + aSts1, t2, t3);
        const float4* s1 = reinterpret_cast<const float4*>(
            X0 + (size_t)(m00 + aRowG) * F_IN + BK + aSeg * 16);
        sA[0] = s1[0]; sA[1] = s1[1]; sA[2] = s1[2]; sA[3] = s1[3];
        CP_WAIT0();
        __syncthreads();
    }

    // flat-stream counters: (k, c) for current, +1 (prefetch), +2 (A staging)
    int k0 = 0, c0 = 0;
    int k1 = 0, c1 = 1;
    int k2 = 0, c2 = 2;

    for (int t = 0; t < nT; ++t) {
        const int p = t & 1;
        const uint32_t bufA  = sb + SM_A0 + p * 8192;
        const uint32_t bufB  = sb + SM_B  + p * 32768;
        const uint32_t bufAn = sb + SM_A0 + (p ^ 1) * 8192;
        const uint32_t bufBn = sb + SM_B  + (p ^ 1) * 32768;

        // ---- prefetch chunk t+1 (unit k1, chunk c1) ----
        if (t + 1 < nT) {
            sts_a16(bufAn + aSts0, sA[0], sA[1]);
            sts_a16(bufAn + aSts1, sA[2], sA[3]);
            const int nh1 = U_NH(cta + k1 * NCTA);
            const __half* src = g_W1h + (size_t)(nh1 * BN + bRow0) * F_IN + c1 * BK + bSeg * 8;
#pragma unroll
            for (int j = 0; j < 8; ++j)
                CP_ASYNC16(bufBn + (uint32_t)(bRow0 + 32 * j) * 128 + bDstSw,
                           src + (size_t)(32 * j) * F_IN);
            CP_COMMIT();
        }
        // ---- stage A LDG for chunk t+2 (unit k2, chunk c2) ----
        if (t + 2 < nT) {
            const int uid2 = cta + k2 * NCTA;
            const float* X = U_PASS(uid2) ? nstm : stm;
            const float4* s = reinterpret_cast<const float4*>(
                X + (size_t)(U_M0(uid2) + aRowG) * F_IN + c2 * BK + aSeg * 16);
            sA[0] = s[0]; sA[1] = s[1]; sA[2] = s[2]; sA[3] = s[3];
        }

        // ---- compute chunk t ----
#pragma unroll
        for (int ks = 0; ks < 4; ++ks) {
            const uint32_t kx = (uint32_t)(ks << 5);
            uint32_t a0[4], a1[4];
            LDSM_X4(a0[0], a0[1], a0[2], a0[3], bufA + aOff +        (aXor ^ kx));
            LDSM_X4(a1[0], a1[1], a1[2], a1[3], bufA + aOff + 2048 + (aXor ^ kx));
            uint32_t b[8][2];
#pragma unroll
            for (int nt2 = 0; nt2 < 4; ++nt2) {
                uint32_t r0, r1, r2, r3;
                LDSM_X4(r0, r1, r2, r3, bufB + bOff + nt2 * 2048 + (bXor ^ kx));
                b[nt2 * 2][0] = r0;     b[nt2 * 2][1] = r1;
                b[nt2 * 2 + 1][0] = r2; b[nt2 * 2 + 1][1] = r3;
            }
#pragma unroll
            for (int nt = 0; nt < 8; ++nt) {
                MMA16816(acc[0][nt], a0, b[nt]);
                MMA16816(acc[1][nt], a1, b[nt]);
            }
        }

        // ---- unit boundary: epilogue + partial write ----
        if (c0 == NCHUNK - 1) {
            const int uid = cta + k0 * NCTA;
            const int m0 = U_M0(uid), pass = U_PASS(uid), nh = U_NH(uid);
            const int w2o = pass * F_OUT;
            const int nbase = nh * BN;
#pragma unroll
            for (int mt = 0; mt < 2; ++mt) {
#pragma unroll
                for (int nt = 0; nt < 8; ++nt) {
                    const int gn = nbase + warpN * 64 + nt * 8 + (lane & 3) * 2;
                    const float2 bv = __ldg(reinterpret_cast<const float2*>(b1 + gn));
                    const float2 wv = __ldg(reinterpret_cast<const float2*>(W2 + w2o + gn));
                    float h;
                    h = fminf(fmaxf(acc[mt][nt][0] + bv.x, 0.f), 1.f); rowsum[mt*2+0] = fmaf(h, wv.x, rowsum[mt*2+0]);
                    h = fminf(fmaxf(acc[mt][nt][1] + bv.y, 0.f), 1.f); rowsum[mt*2+0] = fmaf(h, wv.y, rowsum[mt*2+0]);
                    h = fminf(fmaxf(acc[mt][nt][2] + bv.x, 0.f), 1.f); rowsum[mt*2+1] = fmaf(h, wv.x, rowsum[mt*2+1]);
                    h = fminf(fmaxf(acc[mt][nt][3] + bv.y, 0.f), 1.f); rowsum[mt*2+1] = fmaf(h, wv.y, rowsum[mt*2+1]);
                    acc[mt][nt][0] = 0.f; acc[mt][nt][1] = 0.f;
                    acc[mt][nt][2] = 0.f; acc[mt][nt][3] = 0.f;
                }
            }
#pragma unroll
            for (int r = 0; r < 4; ++r) {
                float v = rowsum[r];
                v += __shfl_xor_sync(0xFFFFFFFFu, v, 1);
                v += __shfl_xor_sync(0xFFFFFFFFu, v, 2);
                if ((lane & 3) == 0) {
                    const int row = warpM * 32 + (r >> 1) * 16 + (r & 1) * 8 + (lane >> 2);
                    atomicAdd(&red_s[row], v);
                }
                rowsum[r] = 0.f;
            }
            __syncthreads();
            if (tid < BM) {
                const float v = red_s[tid];
                red_s[tid] = 0.0f;
                g_part[pass * 2 + nh][m0 + tid] = v;
            }
        }

        CP_WAIT0();
        __syncthreads();

        if (++c0 == NCHUNK) { c0 = 0; ++k0; }
        if (++c1 == NCHUNK) { c1 = 0; ++k1; }
        if (++c2 == NCHUNK) { c2 = 0; ++k2; }
    }
}

// ---------------- launch ----------------
extern "C" void kernel_launch(void* const* d_in, const int* in_sizes, int n_in,
                              void* d_out, int out_size) {
    const float* stm  = (const float*)d_in[0];
    const float* nstm = (const float*)d_in[1];
    const float* W1   = (const float*)d_in[2];
    const float* b1   = (const float*)d_in[3];
    const float* W2   = (const float*)d_in[4];
    const float* b2   = (const float*)d_in[5];
    float* out = (float*)d_out;

    cudaFuncSetAttribute(persp_kernel, cudaFuncAttributeMaxDynamicSharedMemorySize, SM_TOTAL);

    convert_w1_kernel<<<48, 512>>>(W1);
    persp_kernel<<<NCTA, NTHREADS, SM_TOTAL>>>(stm, nstm, b1, W2);
    finalize_kernel<<<BATCH / 256, 256>>>(b2, out);
}